// round 1
// baseline (speedup 1.0000x reference)
#include <cuda_runtime.h>
#include <cuda_bf16.h>

#define BDIM 8
#define LDIM 256
#define CDIM 512
#define ODIM 512
#define MTOT (BDIM * LDIM)   // 2048

// -------- scratch (static device globals; no allocation) --------
__device__ float g_pt[BDIM * LDIM * CDIM];      // relu(xt) @ Wp + bp
__device__ float g_pc[BDIM * LDIM * CDIM];      // relu(xd) @ Wc + bc
__device__ float g_scores[BDIM * LDIM * LDIM];  // sigmoid(pt . pc^T), unnormalized
__device__ float g_Ssum[BDIM];                  // per-batch score sums
__device__ float g_cp[BDIM * CDIM];             // unnormalized cp

// -------- fast-but-accurate transcendentals --------
__device__ __forceinline__ float tanh_fast(float x) {
    // tanh(x) = sign(x) * (1 - 2/(exp(2|x|)+1));  |err| ~1e-6
    float ax = fabsf(x);
    float e = __expf(ax + ax);             // MUFU ex2
    float t = 1.0f - __fdividef(2.0f, e + 1.0f);  // MUFU rcp
    return copysignf(t, x);
}

__device__ __forceinline__ float sigmoid_fast(float x) {
    return __fdividef(1.0f, 1.0f + __expf(-x));
}

// ============================================================
// K0: init — zero Ssum/cp, pre-load output with bias bf
// ============================================================
__global__ void init_kernel(const float* __restrict__ bf, float* __restrict__ out) {
    int idx = blockIdx.x * blockDim.x + threadIdx.x;   // 8*512 = 4096
    if (idx < BDIM) g_Ssum[idx] = 0.0f;
    if (idx < BDIM * CDIM) {
        g_cp[idx] = 0.0f;
        out[idx] = bf[idx & (ODIM - 1)];
    }
}

// ============================================================
// K1: projection GEMMs.  P[m,n] = relu(X[m,:]) @ W[:,n] + b[n]
// blockIdx.z == 0: pt = relu(xt)@Wp+bp ;  z == 1: pc = relu(xd)@Wc+bc
// BM=BN=64, BK=16, 256 threads, 4x4 microtile.
// ============================================================
__global__ void proj_gemm(const float* __restrict__ X0, const float* __restrict__ W0,
                          const float* __restrict__ b0,
                          const float* __restrict__ X1, const float* __restrict__ W1,
                          const float* __restrict__ b1) {
    const float* X    = blockIdx.z ? X1 : X0;
    const float* W    = blockIdx.z ? W1 : W0;
    const float* bias = blockIdx.z ? b1 : b0;
    float* P          = blockIdx.z ? g_pc : g_pt;

    __shared__ float As[16][64];
    __shared__ float Bs[16][64];

    const int m0 = blockIdx.y * 64;
    const int n0 = blockIdx.x * 64;
    const int tid = threadIdx.x;

    const int am = tid >> 2;            // 0..63
    const int ak = (tid & 3) * 4;       // 0,4,8,12
    const int bk = tid >> 4;            // 0..15
    const int bn = (tid & 15) * 4;      // 0..60

    const int tx = tid & 15;
    const int ty = tid >> 4;

    float acc[4][4] = {};

    for (int k0 = 0; k0 < CDIM; k0 += 16) {
        float4 av = *reinterpret_cast<const float4*>(&X[(m0 + am) * CDIM + k0 + ak]);
        av.x = fmaxf(av.x, 0.0f); av.y = fmaxf(av.y, 0.0f);
        av.z = fmaxf(av.z, 0.0f); av.w = fmaxf(av.w, 0.0f);
        As[ak + 0][am] = av.x; As[ak + 1][am] = av.y;
        As[ak + 2][am] = av.z; As[ak + 3][am] = av.w;

        float4 bv = *reinterpret_cast<const float4*>(&W[(k0 + bk) * CDIM + n0 + bn]);
        *reinterpret_cast<float4*>(&Bs[bk][bn]) = bv;

        __syncthreads();
        #pragma unroll
        for (int k = 0; k < 16; k++) {
            float4 a = *reinterpret_cast<const float4*>(&As[k][ty * 4]);
            float4 b = *reinterpret_cast<const float4*>(&Bs[k][tx * 4]);
            acc[0][0] = fmaf(a.x, b.x, acc[0][0]); acc[0][1] = fmaf(a.x, b.y, acc[0][1]);
            acc[0][2] = fmaf(a.x, b.z, acc[0][2]); acc[0][3] = fmaf(a.x, b.w, acc[0][3]);
            acc[1][0] = fmaf(a.y, b.x, acc[1][0]); acc[1][1] = fmaf(a.y, b.y, acc[1][1]);
            acc[1][2] = fmaf(a.y, b.z, acc[1][2]); acc[1][3] = fmaf(a.y, b.w, acc[1][3]);
            acc[2][0] = fmaf(a.z, b.x, acc[2][0]); acc[2][1] = fmaf(a.z, b.y, acc[2][1]);
            acc[2][2] = fmaf(a.z, b.z, acc[2][2]); acc[2][3] = fmaf(a.z, b.w, acc[2][3]);
            acc[3][0] = fmaf(a.w, b.x, acc[3][0]); acc[3][1] = fmaf(a.w, b.y, acc[3][1]);
            acc[3][2] = fmaf(a.w, b.z, acc[3][2]); acc[3][3] = fmaf(a.w, b.w, acc[3][3]);
        }
        __syncthreads();
    }

    #pragma unroll
    for (int i = 0; i < 4; i++) {
        int m = m0 + ty * 4 + i;
        #pragma unroll
        for (int j = 0; j < 4; j++) {
            int n = n0 + tx * 4 + j;
            P[m * CDIM + n] = acc[i][j] + bias[n];
        }
    }
}

// ============================================================
// K2: scores[b,i,j] = sigmoid(dot(pt[b,i,:], pc[b,j,:])); also
// accumulate per-batch sum into g_Ssum.  BM=BN=64, BK=16.
// ============================================================
__global__ void score_gemm() {
    const int b = blockIdx.z;
    const float* A = g_pt + b * LDIM * CDIM;
    const float* B = g_pc + b * LDIM * CDIM;

    __shared__ float As[16][64];
    __shared__ float Bs[16][64];

    const int i0 = blockIdx.y * 64;
    const int j0 = blockIdx.x * 64;
    const int tid = threadIdx.x;

    const int am = tid >> 2;
    const int ak = (tid & 3) * 4;
    const int tx = tid & 15;
    const int ty = tid >> 4;

    float acc[4][4] = {};

    for (int k0 = 0; k0 < CDIM; k0 += 16) {
        float4 av = *reinterpret_cast<const float4*>(&A[(i0 + am) * CDIM + k0 + ak]);
        As[ak + 0][am] = av.x; As[ak + 1][am] = av.y;
        As[ak + 2][am] = av.z; As[ak + 3][am] = av.w;
        float4 bv = *reinterpret_cast<const float4*>(&B[(j0 + am) * CDIM + k0 + ak]);
        Bs[ak + 0][am] = bv.x; Bs[ak + 1][am] = bv.y;
        Bs[ak + 2][am] = bv.z; Bs[ak + 3][am] = bv.w;

        __syncthreads();
        #pragma unroll
        for (int k = 0; k < 16; k++) {
            float4 a = *reinterpret_cast<const float4*>(&As[k][ty * 4]);
            float4 b4 = *reinterpret_cast<const float4*>(&Bs[k][tx * 4]);
            acc[0][0] = fmaf(a.x, b4.x, acc[0][0]); acc[0][1] = fmaf(a.x, b4.y, acc[0][1]);
            acc[0][2] = fmaf(a.x, b4.z, acc[0][2]); acc[0][3] = fmaf(a.x, b4.w, acc[0][3]);
            acc[1][0] = fmaf(a.y, b4.x, acc[1][0]); acc[1][1] = fmaf(a.y, b4.y, acc[1][1]);
            acc[1][2] = fmaf(a.y, b4.z, acc[1][2]); acc[1][3] = fmaf(a.y, b4.w, acc[1][3]);
            acc[2][0] = fmaf(a.z, b4.x, acc[2][0]); acc[2][1] = fmaf(a.z, b4.y, acc[2][1]);
            acc[2][2] = fmaf(a.z, b4.z, acc[2][2]); acc[2][3] = fmaf(a.z, b4.w, acc[2][3]);
            acc[3][0] = fmaf(a.w, b4.x, acc[3][0]); acc[3][1] = fmaf(a.w, b4.y, acc[3][1]);
            acc[3][2] = fmaf(a.w, b4.z, acc[3][2]); acc[3][3] = fmaf(a.w, b4.w, acc[3][3]);
        }
        __syncthreads();
    }

    float lsum = 0.0f;
    float* Srow = g_scores + b * LDIM * LDIM;
    #pragma unroll
    for (int i = 0; i < 4; i++) {
        int ii = i0 + ty * 4 + i;
        #pragma unroll
        for (int j = 0; j < 4; j++) {
            int jj = j0 + tx * 4 + j;
            float s = sigmoid_fast(acc[i][j]);
            Srow[ii * LDIM + jj] = s;
            lsum += s;
        }
    }
    // block reduce lsum -> one atomicAdd
    #pragma unroll
    for (int off = 16; off; off >>= 1)
        lsum += __shfl_xor_sync(0xFFFFFFFFu, lsum, off);
    __shared__ float red[8];
    if ((tid & 31) == 0) red[tid >> 5] = lsum;
    __syncthreads();
    if (tid == 0) {
        float s = 0.0f;
        #pragma unroll
        for (int w = 0; w < 8; w++) s += red[w];
        atomicAdd(&g_Ssum[b], s);
    }
}

// ============================================================
// K3: cp_unnorm[b,c] = sum_{i,j} tanh(xd[b,i,c]*xt[b,j,c]) * scores[b,i,j]
// block = (i-tile of 4, batch), 512 threads = channels. MUFU-bound.
// ============================================================
__global__ void __launch_bounds__(512) cp_kernel(const float* __restrict__ xd,
                                                 const float* __restrict__ xt) {
    const int b = blockIdx.y;
    const int i0 = blockIdx.x * 4;
    const int c = threadIdx.x;

    __shared__ float ws[4][LDIM];
    for (int t = threadIdx.x; t < 4 * LDIM; t += 512) {
        int ii = t >> 8, j = t & (LDIM - 1);
        ws[ii][j] = g_scores[b * LDIM * LDIM + (i0 + ii) * LDIM + j];
    }

    const float* xdp = xd + ((size_t)(b * LDIM + i0)) * CDIM + c;
    const float xd0 = xdp[0 * CDIM];
    const float xd1 = xdp[1 * CDIM];
    const float xd2 = xdp[2 * CDIM];
    const float xd3 = xdp[3 * CDIM];
    __syncthreads();

    const float* xtp = xt + ((size_t)(b * LDIM)) * CDIM + c;
    float acc = 0.0f;
    #pragma unroll 4
    for (int j = 0; j < LDIM; j++) {
        float xtv = __ldg(&xtp[(size_t)j * CDIM]);
        acc = fmaf(tanh_fast(xd0 * xtv), ws[0][j], acc);
        acc = fmaf(tanh_fast(xd1 * xtv), ws[1][j], acc);
        acc = fmaf(tanh_fast(xd2 * xtv), ws[2][j], acc);
        acc = fmaf(tanh_fast(xd3 * xtv), ws[3][j], acc);
    }
    atomicAdd(&g_cp[b * CDIM + c], acc);
}

// ============================================================
// K4: out[b,o] += (cp[b,:]/S_b) @ Wf[:,o]   (out pre-seeded with bf)
// grid (8 batches, 4 c-chunks of 128), 512 threads = o.
// ============================================================
__global__ void out_gemm(const float* __restrict__ Wf, float* __restrict__ out) {
    const int b = blockIdx.x;
    const int c0 = blockIdx.y * 128;
    const int o = threadIdx.x;

    __shared__ float cps[128];
    float inv = __fdividef(1.0f, g_Ssum[b]);
    if (threadIdx.x < 128)
        cps[threadIdx.x] = g_cp[b * CDIM + c0 + threadIdx.x] * inv;
    __syncthreads();

    float acc = 0.0f;
    #pragma unroll 8
    for (int cc = 0; cc < 128; cc++)
        acc = fmaf(cps[cc], Wf[(c0 + cc) * ODIM + o], acc);
    atomicAdd(&out[b * ODIM + o], acc);
}

// ============================================================
extern "C" void kernel_launch(void* const* d_in, const int* in_sizes, int n_in,
                              void* d_out, int out_size) {
    const float* xd = (const float*)d_in[0];
    const float* xt = (const float*)d_in[1];
    const float* Wc = (const float*)d_in[2];
    const float* bc = (const float*)d_in[3];
    const float* Wp = (const float*)d_in[4];
    const float* bp = (const float*)d_in[5];
    const float* Wf = (const float*)d_in[6];
    const float* bf = (const float*)d_in[7];
    float* out = (float*)d_out;

    init_kernel<<<8, 512>>>(bf, out);
    // z=0: pt = relu(xt)@Wp+bp ; z=1: pc = relu(xd)@Wc+bc
    proj_gemm<<<dim3(CDIM / 64, MTOT / 64, 2), 256>>>(xt, Wp, bp, xd, Wc, bc);
    score_gemm<<<dim3(LDIM / 64, LDIM / 64, BDIM), 256>>>();
    cp_kernel<<<dim3(LDIM / 4, BDIM), 512>>>(xd, xt);
    out_gemm<<<dim3(BDIM, 4), 512>>>(Wf, out);
}

// round 2
// speedup vs baseline: 1.4007x; 1.4007x over previous
#include <cuda_runtime.h>
#include <cuda_bf16.h>

#define BDIM 8
#define LDIM 256
#define CDIM 512
#define ODIM 512
#define MTOT (BDIM * LDIM)   // 2048

// -------- scratch (static device globals; no allocation) --------
__device__ float g_pt[BDIM * LDIM * CDIM];      // relu(xt) @ Wp + bp
__device__ float g_pc[BDIM * LDIM * CDIM];      // relu(xd) @ Wc + bc
__device__ float g_scores[BDIM * LDIM * LDIM];  // sigmoid(pt . pc^T), unnormalized
__device__ float g_Ssum[BDIM];                  // per-batch score sums
__device__ float g_cp[BDIM * CDIM];             // unnormalized cp

// -------- transcendentals --------
__device__ __forceinline__ float tanh_mufu(float x) {
    float y;
    asm("tanh.approx.f32 %0, %1;" : "=f"(y) : "f"(x));   // 1 MUFU
    return y;
}

__device__ __forceinline__ float sigmoid_fast(float x) {
    return __fdividef(1.0f, 1.0f + __expf(-x));
}

// ============================================================
// K0: init — zero Ssum/cp, pre-load output with bias bf
// ============================================================
__global__ void init_kernel(const float* __restrict__ bf, float* __restrict__ out) {
    int idx = blockIdx.x * blockDim.x + threadIdx.x;   // 8*512 = 4096
    if (idx < BDIM) g_Ssum[idx] = 0.0f;
    if (idx < BDIM * CDIM) {
        g_cp[idx] = 0.0f;
        out[idx] = bf[idx & (ODIM - 1)];
    }
}

// ============================================================
// K1: projection GEMMs.  P[m,n] = relu(X[m,:]) @ W[:,n] + b[n]
// z==0: pt = relu(xt)@Wp+bp ; z==1: pc = relu(xd)@Wc+bc
// BM=128, BN=64, BK=16, 256 threads, 8x4 microtile.
// ============================================================
__global__ void __launch_bounds__(256) proj_gemm(
        const float* __restrict__ X0, const float* __restrict__ W0,
        const float* __restrict__ b0,
        const float* __restrict__ X1, const float* __restrict__ W1,
        const float* __restrict__ b1) {
    const float* X    = blockIdx.z ? X1 : X0;
    const float* W    = blockIdx.z ? W1 : W0;
    const float* bias = blockIdx.z ? b1 : b0;
    float* P          = blockIdx.z ? g_pc : g_pt;

    __shared__ float As[16][128];
    __shared__ float Bs[16][64];

    const int m0 = blockIdx.y * 128;
    const int n0 = blockIdx.x * 64;
    const int tid = threadIdx.x;

    // A tile load: 128 rows x 16 k = 2048 floats; 8 per thread (2 float4)
    const int am = tid >> 1;             // 0..127
    const int ak = (tid & 1) * 8;        // 0 or 8
    // B tile load: 16 k x 64 n = 1024 floats; 4 per thread (1 float4)
    const int bk = tid >> 4;             // 0..15
    const int bn = (tid & 15) * 4;       // 0..60

    const int tx = tid & 15;             // 4-col group
    const int ty = tid >> 4;             // 8-row group

    float acc[8][4] = {};

    for (int k0 = 0; k0 < CDIM; k0 += 16) {
        #pragma unroll
        for (int h = 0; h < 2; h++) {
            float4 av = *reinterpret_cast<const float4*>(&X[(m0 + am) * CDIM + k0 + ak + h * 4]);
            av.x = fmaxf(av.x, 0.0f); av.y = fmaxf(av.y, 0.0f);
            av.z = fmaxf(av.z, 0.0f); av.w = fmaxf(av.w, 0.0f);
            As[ak + h * 4 + 0][am] = av.x; As[ak + h * 4 + 1][am] = av.y;
            As[ak + h * 4 + 2][am] = av.z; As[ak + h * 4 + 3][am] = av.w;
        }
        float4 bv = *reinterpret_cast<const float4*>(&W[(k0 + bk) * CDIM + n0 + bn]);
        *reinterpret_cast<float4*>(&Bs[bk][bn]) = bv;

        __syncthreads();
        #pragma unroll
        for (int k = 0; k < 16; k++) {
            float4 a0 = *reinterpret_cast<const float4*>(&As[k][ty * 8]);
            float4 a1 = *reinterpret_cast<const float4*>(&As[k][ty * 8 + 4]);
            float4 b4 = *reinterpret_cast<const float4*>(&Bs[k][tx * 4]);
            const float ar[8] = {a0.x, a0.y, a0.z, a0.w, a1.x, a1.y, a1.z, a1.w};
            #pragma unroll
            for (int i = 0; i < 8; i++) {
                acc[i][0] = fmaf(ar[i], b4.x, acc[i][0]);
                acc[i][1] = fmaf(ar[i], b4.y, acc[i][1]);
                acc[i][2] = fmaf(ar[i], b4.z, acc[i][2]);
                acc[i][3] = fmaf(ar[i], b4.w, acc[i][3]);
            }
        }
        __syncthreads();
    }

    #pragma unroll
    for (int i = 0; i < 8; i++) {
        int m = m0 + ty * 8 + i;
        #pragma unroll
        for (int j = 0; j < 4; j++) {
            int n = n0 + tx * 4 + j;
            P[m * CDIM + n] = acc[i][j] + bias[n];
        }
    }
}

// ============================================================
// K2: scores[b,i,j] = sigmoid(dot(pt[b,i,:], pc[b,j,:])); also
// accumulate per-batch sum into g_Ssum.  BM=BN=64, BK=16.
// ============================================================
__global__ void __launch_bounds__(256) score_gemm() {
    const int b = blockIdx.z;
    const float* A = g_pt + b * LDIM * CDIM;
    const float* B = g_pc + b * LDIM * CDIM;

    __shared__ float As[16][64];
    __shared__ float Bs[16][64];

    const int i0 = blockIdx.y * 64;
    const int j0 = blockIdx.x * 64;
    const int tid = threadIdx.x;

    const int am = tid >> 2;
    const int ak = (tid & 3) * 4;
    const int tx = tid & 15;
    const int ty = tid >> 4;

    float acc[4][4] = {};

    for (int k0 = 0; k0 < CDIM; k0 += 16) {
        float4 av = *reinterpret_cast<const float4*>(&A[(i0 + am) * CDIM + k0 + ak]);
        As[ak + 0][am] = av.x; As[ak + 1][am] = av.y;
        As[ak + 2][am] = av.z; As[ak + 3][am] = av.w;
        float4 bv = *reinterpret_cast<const float4*>(&B[(j0 + am) * CDIM + k0 + ak]);
        Bs[ak + 0][am] = bv.x; Bs[ak + 1][am] = bv.y;
        Bs[ak + 2][am] = bv.z; Bs[ak + 3][am] = bv.w;

        __syncthreads();
        #pragma unroll
        for (int k = 0; k < 16; k++) {
            float4 a = *reinterpret_cast<const float4*>(&As[k][ty * 4]);
            float4 b4 = *reinterpret_cast<const float4*>(&Bs[k][tx * 4]);
            acc[0][0] = fmaf(a.x, b4.x, acc[0][0]); acc[0][1] = fmaf(a.x, b4.y, acc[0][1]);
            acc[0][2] = fmaf(a.x, b4.z, acc[0][2]); acc[0][3] = fmaf(a.x, b4.w, acc[0][3]);
            acc[1][0] = fmaf(a.y, b4.x, acc[1][0]); acc[1][1] = fmaf(a.y, b4.y, acc[1][1]);
            acc[1][2] = fmaf(a.y, b4.z, acc[1][2]); acc[1][3] = fmaf(a.y, b4.w, acc[1][3]);
            acc[2][0] = fmaf(a.z, b4.x, acc[2][0]); acc[2][1] = fmaf(a.z, b4.y, acc[2][1]);
            acc[2][2] = fmaf(a.z, b4.z, acc[2][2]); acc[2][3] = fmaf(a.z, b4.w, acc[2][3]);
            acc[3][0] = fmaf(a.w, b4.x, acc[3][0]); acc[3][1] = fmaf(a.w, b4.y, acc[3][1]);
            acc[3][2] = fmaf(a.w, b4.z, acc[3][2]); acc[3][3] = fmaf(a.w, b4.w, acc[3][3]);
        }
        __syncthreads();
    }

    float lsum = 0.0f;
    float* Srow = g_scores + b * LDIM * LDIM;
    #pragma unroll
    for (int i = 0; i < 4; i++) {
        int ii = i0 + ty * 4 + i;
        #pragma unroll
        for (int j = 0; j < 4; j++) {
            int jj = j0 + tx * 4 + j;
            float s = sigmoid_fast(acc[i][j]);
            Srow[ii * LDIM + jj] = s;
            lsum += s;
        }
    }
    #pragma unroll
    for (int off = 16; off; off >>= 1)
        lsum += __shfl_xor_sync(0xFFFFFFFFu, lsum, off);
    __shared__ float red[8];
    if ((tid & 31) == 0) red[tid >> 5] = lsum;
    __syncthreads();
    if (tid == 0) {
        float s = 0.0f;
        #pragma unroll
        for (int w = 0; w < 8; w++) s += red[w];
        atomicAdd(&g_Ssum[b], s);
    }
}

// ============================================================
// K3: cp_unnorm[b,c] = sum_{i,j} tanh(xd[b,i,c]*xt[b,j,c]) * scores[b,i,j]
// block = (i-tile of 4, batch), 512 threads = channels. MUFU.TANH-bound.
// ============================================================
__global__ void __launch_bounds__(512) cp_kernel(const float* __restrict__ xd,
                                                 const float* __restrict__ xt) {
    const int b = blockIdx.y;
    const int i0 = blockIdx.x * 4;
    const int c = threadIdx.x;

    // scores for the 4 i-rows, packed as float4 per j
    __shared__ float4 ws4[LDIM];
    {
        float* wsf = reinterpret_cast<float*>(ws4);
        const float* src = g_scores + (size_t)b * LDIM * LDIM + (size_t)i0 * LDIM;
        for (int t = threadIdx.x; t < 4 * LDIM; t += 512) {
            int i = t >> 8;             // 0..3
            int j = t & (LDIM - 1);
            wsf[(j << 2) | i] = src[i * LDIM + j];
        }
    }

    const float* xdp = xd + ((size_t)(b * LDIM + i0)) * CDIM + c;
    const float xd0 = xdp[0 * CDIM];
    const float xd1 = xdp[1 * CDIM];
    const float xd2 = xdp[2 * CDIM];
    const float xd3 = xdp[3 * CDIM];
    __syncthreads();

    const float* xtp = xt + ((size_t)(b * LDIM)) * CDIM + c;
    float acc = 0.0f;
    #pragma unroll 4
    for (int j = 0; j < LDIM; j++) {
        float xtv = __ldg(&xtp[(size_t)j * CDIM]);
        float4 w = ws4[j];
        acc = fmaf(tanh_mufu(xd0 * xtv), w.x, acc);
        acc = fmaf(tanh_mufu(xd1 * xtv), w.y, acc);
        acc = fmaf(tanh_mufu(xd2 * xtv), w.z, acc);
        acc = fmaf(tanh_mufu(xd3 * xtv), w.w, acc);
    }
    atomicAdd(&g_cp[b * CDIM + c], acc);
}

// ============================================================
// K4: out[b,o] += (cp[b,:]/S_b) @ Wf[:,o]   (out pre-seeded with bf)
// ============================================================
__global__ void out_gemm(const float* __restrict__ Wf, float* __restrict__ out) {
    const int b = blockIdx.x;
    const int c0 = blockIdx.y * 128;
    const int o = threadIdx.x;

    __shared__ float cps[128];
    float inv = __fdividef(1.0f, g_Ssum[b]);
    if (threadIdx.x < 128)
        cps[threadIdx.x] = g_cp[b * CDIM + c0 + threadIdx.x] * inv;
    __syncthreads();

    float acc = 0.0f;
    #pragma unroll 8
    for (int cc = 0; cc < 128; cc++)
        acc = fmaf(cps[cc], Wf[(c0 + cc) * ODIM + o], acc);
    atomicAdd(&out[b * ODIM + o], acc);
}

// ============================================================
extern "C" void kernel_launch(void* const* d_in, const int* in_sizes, int n_in,
                              void* d_out, int out_size) {
    const float* xd = (const float*)d_in[0];
    const float* xt = (const float*)d_in[1];
    const float* Wc = (const float*)d_in[2];
    const float* bc = (const float*)d_in[3];
    const float* Wp = (const float*)d_in[4];
    const float* bp = (const float*)d_in[5];
    const float* Wf = (const float*)d_in[6];
    const float* bf = (const float*)d_in[7];
    float* out = (float*)d_out;

    init_kernel<<<8, 512>>>(bf, out);
    proj_gemm<<<dim3(CDIM / 64, MTOT / 128, 2), 256>>>(xt, Wp, bp, xd, Wc, bc);
    score_gemm<<<dim3(LDIM / 64, LDIM / 64, BDIM), 256>>>();
    cp_kernel<<<dim3(LDIM / 4, BDIM), 512>>>(xd, xt);
    out_gemm<<<dim3(BDIM, 4), 512>>>(Wf, out);
}

// round 6
// speedup vs baseline: 1.6720x; 1.1937x over previous
#include <cuda_runtime.h>
#include <cuda_bf16.h>
#include <cstdint>

#define BDIM 8
#define LDIM 256
#define CDIM 512
#define ODIM 512
#define MTOT (BDIM * LDIM)   // 2048
#define KSPL 1536            // 3*CDIM split-K
#define NCHUNK 24            // KSPL / 64  (k-chunk = 64 bf16? no: chunk = 32 -> 48; we use 32)
#define SPAD 40              // smem row stride (32 + 8 pad) in bf16

// -------- scratch (static device globals; no allocation) --------
__device__ __align__(16) __nv_bfloat16 g_xt_s[MTOT * KSPL];   // relu(xt) split [hi,hi,lo]
__device__ __align__(16) __nv_bfloat16 g_xd_s[MTOT * KSPL];   // relu(xd) split [hi,hi,lo]
__device__ __align__(16) __nv_bfloat16 g_Wp_s[CDIM * KSPL];   // Wp^T split [hi,lo,hi]
__device__ __align__(16) __nv_bfloat16 g_Wc_s[CDIM * KSPL];   // Wc^T split [hi,lo,hi]
__device__ __align__(16) __nv_bfloat16 g_pt_s[MTOT * KSPL];   // pt split [hi,hi,lo]
__device__ __align__(16) __nv_bfloat16 g_pc_s[MTOT * KSPL];   // pc split [hi,lo,hi]
__device__ float g_scores[BDIM * LDIM * LDIM];
__device__ float g_Ssum[BDIM];
__device__ float g_cp[BDIM * CDIM];

// -------- transcendentals --------
__device__ __forceinline__ float tanh_mufu(float x) {
    float y;
    asm("tanh.approx.f32 %0, %1;" : "=f"(y) : "f"(x));
    return y;
}
__device__ __forceinline__ float sigmoid_fast(float x) {
    return __fdividef(1.0f, 1.0f + __expf(-x));
}

// -------- helpers --------
__device__ __forceinline__ uint32_t smem_u32(const void* p) {
    uint32_t a;
    asm("{ .reg .u64 t; cvta.to.shared.u64 t, %1; cvt.u32.u64 %0, t; }" : "=r"(a) : "l"(p));
    return a;
}
__device__ __forceinline__ void ldsm4(uint32_t* r, uint32_t addr) {
    asm volatile("ldmatrix.sync.aligned.m8n8.x4.shared.b16 {%0,%1,%2,%3}, [%4];"
                 : "=r"(r[0]), "=r"(r[1]), "=r"(r[2]), "=r"(r[3]) : "r"(addr));
}
__device__ __forceinline__ void mma_bf16(float* c, const uint32_t* a,
                                         uint32_t b0, uint32_t b1) {
    asm volatile(
        "mma.sync.aligned.m16n8k16.row.col.f32.bf16.bf16.f32 "
        "{%0,%1,%2,%3}, {%4,%5,%6,%7}, {%8,%9}, {%0,%1,%2,%3};"
        : "+f"(c[0]), "+f"(c[1]), "+f"(c[2]), "+f"(c[3])
        : "r"(a[0]), "r"(a[1]), "r"(a[2]), "r"(a[3]), "r"(b0), "r"(b1));
}
__device__ __forceinline__ void split2(float v, unsigned short& h, unsigned short& l) {
    __nv_bfloat16 hb = __float2bfloat16(v);
    __nv_bfloat16 lb = __float2bfloat16(v - __bfloat162float(hb));
    h = __bfloat16_as_ushort(hb);
    l = __bfloat16_as_ushort(lb);
}

// ============================================================
// HMMA mainloop: C[BM,BN] += A[BM,K'] . B[BN,K']^T over K'=1536,
// k-chunk 32, double-buffered smem, 256 threads = 8 warps (NWM x NWN).
// acc layout: acc[im*NJ + jn][4], MI = BM/NWM/16, NJ = BN/NWN/8.
// ============================================================
template <int BM, int BN, int NWM, int NWN>
__device__ __forceinline__ void hmma_mainloop(
        const __nv_bfloat16* __restrict__ A0,   // row stride KSPL
        const __nv_bfloat16* __restrict__ B0,   // row stride KSPL
        __nv_bfloat16* sA, __nv_bfloat16* sB,   // [2][BM*SPAD], [2][BN*SPAD]
        float (*acc)[4], int tid) {
    constexpr int MI = BM / NWM / 16;
    constexpr int NJ = BN / NWN / 8;
    constexpr int NJ2 = NJ / 2;
    constexpr int NA = BM * 4 / 256;    // uint4 loads per thread per chunk (A)
    constexpr int NB = BN * 4 / 256;
    constexpr int NCH = KSPL / 32;      // 48 chunks of k=32

    const int lane = tid & 31;
    const int warp = tid >> 5;
    const int wm = warp % NWM;
    const int wn = warp / NWM;
    const uint32_t aBase = smem_u32(sA);
    const uint32_t bBase = smem_u32(sB);

    const int arow = (tid + 0) >> 2;      // reused pattern below with idx offsets
    (void)arow;

    uint4 ra[NA], rb[NB];

    // ---- load chunk 0 ----
    #pragma unroll
    for (int q = 0; q < NA; q++) {
        int idx = tid + q * 256, row = idx >> 2, kq = idx & 3;
        ra[q] = *reinterpret_cast<const uint4*>(A0 + (size_t)row * KSPL + kq * 8);
    }
    #pragma unroll
    for (int q = 0; q < NB; q++) {
        int idx = tid + q * 256, row = idx >> 2, kq = idx & 3;
        rb[q] = *reinterpret_cast<const uint4*>(B0 + (size_t)row * KSPL + kq * 8);
    }
    #pragma unroll
    for (int q = 0; q < NA; q++) {
        int idx = tid + q * 256, row = idx >> 2, kq = idx & 3;
        *reinterpret_cast<uint4*>(sA + row * SPAD + kq * 8) = ra[q];
    }
    #pragma unroll
    for (int q = 0; q < NB; q++) {
        int idx = tid + q * 256, row = idx >> 2, kq = idx & 3;
        *reinterpret_cast<uint4*>(sB + row * SPAD + kq * 8) = rb[q];
    }
    __syncthreads();

    int buf = 0;
    for (int c = 0; c < NCH; c++) {
        if (c + 1 < NCH) {
            #pragma unroll
            for (int q = 0; q < NA; q++) {
                int idx = tid + q * 256, row = idx >> 2, kq = idx & 3;
                ra[q] = *reinterpret_cast<const uint4*>(
                    A0 + (size_t)row * KSPL + (c + 1) * 32 + kq * 8);
            }
            #pragma unroll
            for (int q = 0; q < NB; q++) {
                int idx = tid + q * 256, row = idx >> 2, kq = idx & 3;
                rb[q] = *reinterpret_cast<const uint4*>(
                    B0 + (size_t)row * KSPL + (c + 1) * 32 + kq * 8);
            }
        }

        // ---- compute on smem[buf] ----
        #pragma unroll
        for (int kk = 0; kk < 32; kk += 16) {
            uint32_t af[MI][4];
            #pragma unroll
            for (int im = 0; im < MI; im++) {
                int row = wm * (BM / NWM) + im * 16 + (lane & 15);
                int col = kk + (lane >> 4) * 8;
                ldsm4(af[im], aBase + (uint32_t)(buf * BM * SPAD + row * SPAD + col) * 2);
            }
            #pragma unroll
            for (int j2 = 0; j2 < NJ2; j2++) {
                uint32_t bfr[4];
                int row = wn * (BN / NWN) + j2 * 16 + (lane & 15);
                int col = kk + (lane >> 4) * 8;
                ldsm4(bfr, bBase + (uint32_t)(buf * BN * SPAD + row * SPAD + col) * 2);
                #pragma unroll
                for (int im = 0; im < MI; im++) {
                    mma_bf16(acc[im * NJ + 2 * j2 + 0], af[im], bfr[0], bfr[2]);
                    mma_bf16(acc[im * NJ + 2 * j2 + 1], af[im], bfr[1], bfr[3]);
                }
            }
        }

        if (c + 1 < NCH) {
            int nb = buf ^ 1;
            #pragma unroll
            for (int q = 0; q < NA; q++) {
                int idx = tid + q * 256, row = idx >> 2, kq = idx & 3;
                *reinterpret_cast<uint4*>(sA + nb * BM * SPAD + row * SPAD + kq * 8) = ra[q];
            }
            #pragma unroll
            for (int q = 0; q < NB; q++) {
                int idx = tid + q * 256, row = idx >> 2, kq = idx & 3;
                *reinterpret_cast<uint4*>(sB + nb * BN * SPAD + row * SPAD + kq * 8) = rb[q];
            }
        }
        __syncthreads();
        buf ^= 1;
    }
}

// ============================================================
// K0: init
// ============================================================
__global__ void init_kernel(const float* __restrict__ bf, float* __restrict__ out) {
    int idx = blockIdx.x * blockDim.x + threadIdx.x;
    if (idx < BDIM) g_Ssum[idx] = 0.0f;
    if (idx < BDIM * CDIM) {
        g_cp[idx] = 0.0f;
        out[idx] = bf[idx & (ODIM - 1)];
    }
}

// ============================================================
// K1: split X (with relu) -> [hi, hi, lo] bf16, K'=1536
// ============================================================
__global__ void split_x_kernel(const float* __restrict__ xt, const float* __restrict__ xd) {
    const float* X = blockIdx.z ? xd : xt;
    __nv_bfloat16* O = blockIdx.z ? g_xd_s : g_xt_s;
    int gid = blockIdx.x * blockDim.x + threadIdx.x;
    if (gid >= MTOT * CDIM / 4) return;
    int m = gid >> 7;
    int k4 = (gid & 127) * 4;
    float4 v = *reinterpret_cast<const float4*>(X + (size_t)m * CDIM + k4);
    float vv[4] = {fmaxf(v.x, 0.f), fmaxf(v.y, 0.f), fmaxf(v.z, 0.f), fmaxf(v.w, 0.f)};
    unsigned short h[4], l[4];
    #pragma unroll
    for (int i = 0; i < 4; i++) split2(vv[i], h[i], l[i]);
    uint2 hp = make_uint2((uint32_t)h[0] | ((uint32_t)h[1] << 16),
                          (uint32_t)h[2] | ((uint32_t)h[3] << 16));
    uint2 lp = make_uint2((uint32_t)l[0] | ((uint32_t)l[1] << 16),
                          (uint32_t)l[2] | ((uint32_t)l[3] << 16));
    size_t base = (size_t)m * KSPL + k4;
    *reinterpret_cast<uint2*>(O + base) = hp;
    *reinterpret_cast<uint2*>(O + base + CDIM) = hp;
    *reinterpret_cast<uint2*>(O + base + 2 * CDIM) = lp;
}

// ============================================================
// K2: split W with transpose: W[k,n] -> Wsplit[n,k'] segs [hi, lo, hi]
// ============================================================
__global__ void split_w_kernel(const float* __restrict__ Wp, const float* __restrict__ Wc) {
    const float* W = blockIdx.z ? Wc : Wp;
    __nv_bfloat16* O = blockIdx.z ? g_Wc_s : g_Wp_s;
    __shared__ float tile[32][33];
    int k0 = blockIdx.x * 32, n0 = blockIdx.y * 32;
    int tx = threadIdx.x, ty = threadIdx.y;
    tile[ty][tx] = W[(size_t)(k0 + ty) * CDIM + n0 + tx];
    __syncthreads();
    float v = tile[tx][ty];
    unsigned short h, l;
    split2(v, h, l);
    size_t base = (size_t)(n0 + ty) * KSPL + k0 + tx;
    O[base] = __ushort_as_bfloat16(h);
    O[base + CDIM] = __ushort_as_bfloat16(l);
    O[base + 2 * CDIM] = __ushort_as_bfloat16(h);
}

// ============================================================
// K3: projection GEMMs (HMMA). z=0: pt -> g_pt_s [hi,hi,lo]
//                              z=1: pc -> g_pc_s [hi,lo,hi]
// 128x128 tile, warps 4x2 (32x64 each): MI=2, NJ=8.
// ============================================================
__global__ void __launch_bounds__(256) proj_hmma(const float* __restrict__ bp,
                                                 const float* __restrict__ bc) {
    __shared__ __align__(16) __nv_bfloat16 sA[2 * 128 * SPAD];
    __shared__ __align__(16) __nv_bfloat16 sB[2 * 128 * SPAD];

    const int tid = threadIdx.x;
    const int z = blockIdx.z;
    const int m0 = blockIdx.y * 128;
    const int n0 = blockIdx.x * 128;

    const __nv_bfloat16* X = z ? g_xd_s : g_xt_s;
    const __nv_bfloat16* Wm = z ? g_Wc_s : g_Wp_s;
    const float* bias = z ? bc : bp;
    __nv_bfloat16* P = z ? g_pc_s : g_pt_s;

    float acc[16][4];
    #pragma unroll
    for (int i = 0; i < 16; i++)
        acc[i][0] = acc[i][1] = acc[i][2] = acc[i][3] = 0.0f;

    hmma_mainloop<128, 128, 4, 2>(X + (size_t)m0 * KSPL, Wm + (size_t)n0 * KSPL,
                                  sA, sB, acc, tid);

    const int lane = tid & 31;
    const int warp = tid >> 5;
    const int wm = warp % 4;
    const int wn = warp / 4;

    #pragma unroll
    for (int im = 0; im < 2; im++) {
        #pragma unroll
        for (int jn = 0; jn < 8; jn++) {
            const float* c = acc[im * 8 + jn];
            int n = n0 + wn * 64 + jn * 8 + (lane & 3) * 2;
            float b0 = __ldg(&bias[n]), b1 = __ldg(&bias[n + 1]);
            int r0 = m0 + wm * 32 + im * 16 + (lane >> 2);
            #pragma unroll
            for (int h = 0; h < 2; h++) {
                int m = r0 + h * 8;
                float v0 = c[2 * h + 0] + b0;
                float v1 = c[2 * h + 1] + b1;
                unsigned short h0, l0, h1, l1;
                split2(v0, h0, l0);
                split2(v1, h1, l1);
                uint32_t hp = (uint32_t)h0 | ((uint32_t)h1 << 16);
                uint32_t lp = (uint32_t)l0 | ((uint32_t)l1 << 16);
                size_t rowoff = (size_t)m * KSPL + n;
                if (z == 0) {   // pt: [hi, hi, lo]
                    *reinterpret_cast<uint32_t*>(P + rowoff) = hp;
                    *reinterpret_cast<uint32_t*>(P + rowoff + CDIM) = hp;
                    *reinterpret_cast<uint32_t*>(P + rowoff + 2 * CDIM) = lp;
                } else {        // pc: [hi, lo, hi]
                    *reinterpret_cast<uint32_t*>(P + rowoff) = hp;
                    *reinterpret_cast<uint32_t*>(P + rowoff + CDIM) = lp;
                    *reinterpret_cast<uint32_t*>(P + rowoff + 2 * CDIM) = hp;
                }
            }
        }
    }
}

// ============================================================
// K4: score GEMM (HMMA): scores[b,i,j] = sigmoid(pt[b,i].pc[b,j]) + batch sums
// 64x64 tile, warps 2x4 (32x16 each): MI=2, NJ=2. grid (4,4,8).
// ============================================================
__global__ void __launch_bounds__(256) score_hmma() {
    __shared__ __align__(16) __nv_bfloat16 sA[2 * 64 * SPAD];
    __shared__ __align__(16) __nv_bfloat16 sB[2 * 64 * SPAD];

    const int tid = threadIdx.x;
    const int b = blockIdx.z;
    const int i0 = blockIdx.y * 64;
    const int j0 = blockIdx.x * 64;

    const __nv_bfloat16* A = g_pt_s + (size_t)(b * LDIM + i0) * KSPL;
    const __nv_bfloat16* B = g_pc_s + (size_t)(b * LDIM + j0) * KSPL;

    float acc[4][4];
    #pragma unroll
    for (int i = 0; i < 4; i++)
        acc[i][0] = acc[i][1] = acc[i][2] = acc[i][3] = 0.0f;

    hmma_mainloop<64, 64, 2, 4>(A, B, sA, sB, acc, tid);

    const int lane = tid & 31;
    const int warp = tid >> 5;
    const int wm = warp % 2;
    const int wn = warp / 2;

    float lsum = 0.0f;
    float* Sb = g_scores + ((size_t)b << 16);
    #pragma unroll
    for (int im = 0; im < 2; im++) {
        #pragma unroll
        for (int jn = 0; jn < 2; jn++) {
            const float* c = acc[im * 2 + jn];
            int j = j0 + wn * 16 + jn * 8 + (lane & 3) * 2;
            int r0 = i0 + wm * 32 + im * 16 + (lane >> 2);
            #pragma unroll
            for (int h = 0; h < 2; h++) {
                int i = r0 + h * 8;
                float s0 = sigmoid_fast(c[2 * h + 0]);
                float s1 = sigmoid_fast(c[2 * h + 1]);
                *reinterpret_cast<float2*>(Sb + (size_t)i * LDIM + j) =
                    make_float2(s0, s1);
                lsum += s0 + s1;
            }
        }
    }
    #pragma unroll
    for (int off = 16; off; off >>= 1)
        lsum += __shfl_xor_sync(0xFFFFFFFFu, lsum, off);
    __shared__ float red[8];
    if (lane == 0) red[warp] = lsum;
    __syncthreads();
    if (tid == 0) {
        float s = 0.0f;
        #pragma unroll
        for (int w = 0; w < 8; w++) s += red[w];
        atomicAdd(&g_Ssum[b], s);
    }
}

// ============================================================
// K5: cp_unnorm[b,c] = sum_{i,j} tanh(xd[b,i,c]*xt[b,j,c]) * scores[b,i,j]
// ============================================================
__global__ void __launch_bounds__(512) cp_kernel(const float* __restrict__ xd,
                                                 const float* __restrict__ xt) {
    const int b = blockIdx.y;
    const int i0 = blockIdx.x * 4;
    const int c = threadIdx.x;

    __shared__ float4 ws4[LDIM];
    {
        float* wsf = reinterpret_cast<float*>(ws4);
        const float* src = g_scores + (size_t)b * LDIM * LDIM + (size_t)i0 * LDIM;
        for (int t = threadIdx.x; t < 4 * LDIM; t += 512) {
            int i = t >> 8, j = t & (LDIM - 1);
            wsf[(j << 2) | i] = src[i * LDIM + j];
        }
    }

    const float* xdp = xd + ((size_t)(b * LDIM + i0)) * CDIM + c;
    const float xd0 = xdp[0 * CDIM];
    const float xd1 = xdp[1 * CDIM];
    const float xd2 = xdp[2 * CDIM];
    const float xd3 = xdp[3 * CDIM];
    __syncthreads();

    const float* xtp = xt + ((size_t)(b * LDIM)) * CDIM + c;
    float acc = 0.0f;
    #pragma unroll 4
    for (int j = 0; j < LDIM; j++) {
        float xtv = __ldg(&xtp[(size_t)j * CDIM]);
        float4 w = ws4[j];
        acc = fmaf(tanh_mufu(xd0 * xtv), w.x, acc);
        acc = fmaf(tanh_mufu(xd1 * xtv), w.y, acc);
        acc = fmaf(tanh_mufu(xd2 * xtv), w.z, acc);
        acc = fmaf(tanh_mufu(xd3 * xtv), w.w, acc);
    }
    atomicAdd(&g_cp[b * CDIM + c], acc);
}

// ============================================================
// K6: out[b,o] += (cp[b,:]/S_b) @ Wf[:,o]
// ============================================================
__global__ void out_gemm(const float* __restrict__ Wf, float* __restrict__ out) {
    const int b = blockIdx.x;
    const int c0 = blockIdx.y * 128;
    const int o = threadIdx.x;

    __shared__ float cps[128];
    float inv = __fdividef(1.0f, g_Ssum[b]);
    if (threadIdx.x < 128)
        cps[threadIdx.x] = g_cp[b * CDIM + c0 + threadIdx.x] * inv;
    __syncthreads();

    float acc = 0.0f;
    #pragma unroll 8
    for (int cc = 0; cc < 128; cc++)
        acc = fmaf(cps[cc], Wf[(c0 + cc) * ODIM + o], acc);
    atomicAdd(&out[b * ODIM + o], acc);
}

// ============================================================
extern "C" void kernel_launch(void* const* d_in, const int* in_sizes, int n_in,
                              void* d_out, int out_size) {
    const float* xd = (const float*)d_in[0];
    const float* xt = (const float*)d_in[1];
    const float* Wc = (const float*)d_in[2];
    const float* bc = (const float*)d_in[3];
    const float* Wp = (const float*)d_in[4];
    const float* bp = (const float*)d_in[5];
    const float* Wf = (const float*)d_in[6];
    const float* bf = (const float*)d_in[7];
    float* out = (float*)d_out;

    init_kernel<<<8, 512>>>(bf, out);
    split_x_kernel<<<dim3(MTOT * CDIM / 4 / 256, 1, 2), 256>>>(xt, xd);
    split_w_kernel<<<dim3(16, 16, 2), dim3(32, 32)>>>(Wp, Wc);
    proj_hmma<<<dim3(CDIM / 128, MTOT / 128, 2), 256>>>(bp, bc);
    score_hmma<<<dim3(LDIM / 64, LDIM / 64, BDIM), 256>>>();
    cp_kernel<<<dim3(LDIM / 4, BDIM), 512>>>(xd, xt);
    out_gemm<<<dim3(BDIM, 4), 512>>>(Wf, out);
}

// round 7
// speedup vs baseline: 1.8404x; 1.1007x over previous
#include <cuda_runtime.h>
#include <cuda_bf16.h>
#include <cstdint>

#define BDIM 8
#define LDIM 256
#define CDIM 512
#define ODIM 512
#define MTOT (BDIM * LDIM)   // 2048
#define KSPL 1536            // 3*CDIM split-K
#define SROWP 72             // smem row stride (64 + 8 pad) bf16
#define SMAT (64 * SROWP)    // one 64x64 tile in smem (elems)

// -------- scratch (static device globals; no allocation) --------
__device__ __align__(16) __nv_bfloat16 g_xt_s[MTOT * KSPL];   // relu(xt) split [hi,hi,lo]
__device__ __align__(16) __nv_bfloat16 g_xd_s[MTOT * KSPL];   // relu(xd) split [hi,hi,lo]
__device__ __align__(16) __nv_bfloat16 g_Wp_s[CDIM * KSPL];   // Wp^T split [hi,lo,hi]
__device__ __align__(16) __nv_bfloat16 g_Wc_s[CDIM * KSPL];   // Wc^T split [hi,lo,hi]
__device__ __align__(16) __nv_bfloat16 g_pt_s[MTOT * KSPL];   // pt split [hi,hi,lo]
__device__ __align__(16) __nv_bfloat16 g_pc_s[MTOT * KSPL];   // pc split [hi,lo,hi]
__device__ float g_scores[BDIM * LDIM * LDIM];
__device__ float g_Ssum[BDIM];
__device__ float g_cp[BDIM * CDIM];

// -------- transcendentals --------
__device__ __forceinline__ float tanh_mufu(float x) {
    float y;
    asm("tanh.approx.f32 %0, %1;" : "=f"(y) : "f"(x));
    return y;
}
__device__ __forceinline__ float sigmoid_fast(float x) {
    return __fdividef(1.0f, 1.0f + __expf(-x));
}

// -------- helpers --------
__device__ __forceinline__ uint32_t smem_u32(const void* p) {
    uint32_t a;
    asm("{ .reg .u64 t; cvta.to.shared.u64 t, %1; cvt.u32.u64 %0, t; }" : "=r"(a) : "l"(p));
    return a;
}
__device__ __forceinline__ void ldsm4(uint32_t* r, uint32_t addr) {
    asm volatile("ldmatrix.sync.aligned.m8n8.x4.shared.b16 {%0,%1,%2,%3}, [%4];"
                 : "=r"(r[0]), "=r"(r[1]), "=r"(r[2]), "=r"(r[3]) : "r"(addr));
}
__device__ __forceinline__ void mma_bf16(float* c, const uint32_t* a,
                                         uint32_t b0, uint32_t b1) {
    asm volatile(
        "mma.sync.aligned.m16n8k16.row.col.f32.bf16.bf16.f32 "
        "{%0,%1,%2,%3}, {%4,%5,%6,%7}, {%8,%9}, {%0,%1,%2,%3};"
        : "+f"(c[0]), "+f"(c[1]), "+f"(c[2]), "+f"(c[3])
        : "r"(a[0]), "r"(a[1]), "r"(a[2]), "r"(a[3]), "r"(b0), "r"(b1));
}
__device__ __forceinline__ void cp_async16(uint32_t dst, const void* src) {
    asm volatile("cp.async.ca.shared.global [%0], [%1], 16;" :: "r"(dst), "l"(src));
}
#define CP_COMMIT() asm volatile("cp.async.commit_group;" ::: "memory")
#define CP_WAIT1()  asm volatile("cp.async.wait_group 1;" ::: "memory")
#define CP_WAIT0()  asm volatile("cp.async.wait_group 0;" ::: "memory")

__device__ __forceinline__ void split2(float v, unsigned short& h, unsigned short& l) {
    __nv_bfloat16 hb = __float2bfloat16(v);
    __nv_bfloat16 lb = __float2bfloat16(v - __bfloat162float(hb));
    h = __bfloat16_as_ushort(hb);
    l = __bfloat16_as_ushort(lb);
}

// ============================================================
// HMMA 64x64 mainloop over K'=1536, BK=64, 2-stage cp.async pipeline.
// NT threads = NWM*NWN warps; warp tile (64/NWM) x (64/NWN).
// smem layout: sm[stage][mat][64*SROWP] bf16, stage in {0,1}, mat A=0,B=1.
// ============================================================
template <int NWM, int NWN, int NT>
__device__ __forceinline__ void hmma_loop64(
        const __nv_bfloat16* __restrict__ A0,   // row stride KSPL
        const __nv_bfloat16* __restrict__ B0,   // row stride KSPL
        __nv_bfloat16* sm, float (*acc)[4], int tid) {
    constexpr int MI = 64 / NWM / 16;
    constexpr int NJ = 64 / NWN / 8;
    constexpr int NJ2 = NJ / 2;
    constexpr int LPT = 1024 / NT;      // uint4 cp.async per thread per stage
    constexpr int NCH = KSPL / 64;      // 24

    const int lane = tid & 31;
    const int warp = tid >> 5;
    const int wm = warp % NWM;
    const int wn = warp / NWM;
    const uint32_t base = smem_u32(sm);

    // issue loads for chunk c into stage s
    auto issue = [&](int s, int c) {
        #pragma unroll
        for (int q = 0; q < LPT; q++) {
            int idx = tid + q * NT;
            int mat = idx >> 9;                 // 0=A, 1=B
            int rem = idx & 511;
            int row = rem >> 3;
            int kq = rem & 7;
            const __nv_bfloat16* g = (mat ? B0 : A0) + (size_t)row * KSPL + c * 64 + kq * 8;
            uint32_t d = base + (uint32_t)((s * 2 + mat) * SMAT + row * SROWP + kq * 8) * 2;
            cp_async16(d, g);
        }
        CP_COMMIT();
    };

    issue(0, 0);

    for (int c = 0; c < NCH; c++) {
        const int s = c & 1;
        if (c + 1 < NCH) {
            issue(s ^ 1, c + 1);
            CP_WAIT1();
        } else {
            CP_WAIT0();
        }
        __syncthreads();

        const uint32_t aBase = base + (uint32_t)(s * 2 * SMAT) * 2;
        const uint32_t bBase = base + (uint32_t)((s * 2 + 1) * SMAT) * 2;
        #pragma unroll
        for (int kk = 0; kk < 64; kk += 16) {
            uint32_t af[MI][4];
            #pragma unroll
            for (int im = 0; im < MI; im++) {
                int row = wm * (64 / NWM) + im * 16 + (lane & 15);
                ldsm4(af[im], aBase + (uint32_t)(row * SROWP + kk + (lane >> 4) * 8) * 2);
            }
            #pragma unroll
            for (int j2 = 0; j2 < NJ2; j2++) {
                uint32_t bfr[4];
                int row = wn * (64 / NWN) + j2 * 16 + (lane & 15);
                ldsm4(bfr, bBase + (uint32_t)(row * SROWP + kk + (lane >> 4) * 8) * 2);
                #pragma unroll
                for (int im = 0; im < MI; im++) {
                    mma_bf16(acc[im * NJ + 2 * j2 + 0], af[im], bfr[0], bfr[2]);
                    mma_bf16(acc[im * NJ + 2 * j2 + 1], af[im], bfr[1], bfr[3]);
                }
            }
        }
        __syncthreads();   // all warps done with stage s before it is reloaded
    }
}

// ============================================================
// K0: init
// ============================================================
__global__ void init_kernel(const float* __restrict__ bf, float* __restrict__ out) {
    int idx = blockIdx.x * blockDim.x + threadIdx.x;
    if (idx < BDIM) g_Ssum[idx] = 0.0f;
    if (idx < BDIM * CDIM) {
        g_cp[idx] = 0.0f;
        out[idx] = bf[idx & (ODIM - 1)];
    }
}

// ============================================================
// K1: split X (with relu) -> [hi, hi, lo] bf16, K'=1536
// ============================================================
__global__ void split_x_kernel(const float* __restrict__ xt, const float* __restrict__ xd) {
    const float* X = blockIdx.z ? xd : xt;
    __nv_bfloat16* O = blockIdx.z ? g_xd_s : g_xt_s;
    int gid = blockIdx.x * blockDim.x + threadIdx.x;
    if (gid >= MTOT * CDIM / 4) return;
    int m = gid >> 7;
    int k4 = (gid & 127) * 4;
    float4 v = *reinterpret_cast<const float4*>(X + (size_t)m * CDIM + k4);
    float vv[4] = {fmaxf(v.x, 0.f), fmaxf(v.y, 0.f), fmaxf(v.z, 0.f), fmaxf(v.w, 0.f)};
    unsigned short h[4], l[4];
    #pragma unroll
    for (int i = 0; i < 4; i++) split2(vv[i], h[i], l[i]);
    uint2 hp = make_uint2((uint32_t)h[0] | ((uint32_t)h[1] << 16),
                          (uint32_t)h[2] | ((uint32_t)h[3] << 16));
    uint2 lp = make_uint2((uint32_t)l[0] | ((uint32_t)l[1] << 16),
                          (uint32_t)l[2] | ((uint32_t)l[3] << 16));
    size_t base = (size_t)m * KSPL + k4;
    *reinterpret_cast<uint2*>(O + base) = hp;
    *reinterpret_cast<uint2*>(O + base + CDIM) = hp;
    *reinterpret_cast<uint2*>(O + base + 2 * CDIM) = lp;
}

// ============================================================
// K2: split W with transpose: W[k,n] -> Wsplit[n,k'] segs [hi, lo, hi]
// ============================================================
__global__ void split_w_kernel(const float* __restrict__ Wp, const float* __restrict__ Wc) {
    const float* W = blockIdx.z ? Wc : Wp;
    __nv_bfloat16* O = blockIdx.z ? g_Wc_s : g_Wp_s;
    __shared__ float tile[32][33];
    int k0 = blockIdx.x * 32, n0 = blockIdx.y * 32;
    int tx = threadIdx.x, ty = threadIdx.y;
    tile[ty][tx] = W[(size_t)(k0 + ty) * CDIM + n0 + tx];
    __syncthreads();
    float v = tile[tx][ty];
    unsigned short h, l;
    split2(v, h, l);
    size_t base = (size_t)(n0 + ty) * KSPL + k0 + tx;
    O[base] = __ushort_as_bfloat16(h);
    O[base + CDIM] = __ushort_as_bfloat16(l);
    O[base + 2 * CDIM] = __ushort_as_bfloat16(h);
}

// ============================================================
// K3: projection GEMMs (HMMA, 64x64 tiles, 128 thr, 2x2 warps).
// z=0: pt -> g_pt_s [hi,hi,lo] ; z=1: pc -> g_pc_s [hi,lo,hi]
// ============================================================
__global__ void __launch_bounds__(128) proj_hmma(const float* __restrict__ bp,
                                                 const float* __restrict__ bc) {
    __shared__ __align__(16) __nv_bfloat16 sm[4 * SMAT];   // 2 stages x {A,B}

    const int tid = threadIdx.x;
    const int z = blockIdx.z;
    const int m0 = blockIdx.y * 64;
    const int n0 = blockIdx.x * 64;

    const __nv_bfloat16* X = z ? g_xd_s : g_xt_s;
    const __nv_bfloat16* Wm = z ? g_Wc_s : g_Wp_s;
    const float* bias = z ? bc : bp;
    __nv_bfloat16* P = z ? g_pc_s : g_pt_s;

    float acc[8][4];   // MI=2, NJ=4
    #pragma unroll
    for (int i = 0; i < 8; i++)
        acc[i][0] = acc[i][1] = acc[i][2] = acc[i][3] = 0.0f;

    hmma_loop64<2, 2, 128>(X + (size_t)m0 * KSPL, Wm + (size_t)n0 * KSPL, sm, acc, tid);

    const int lane = tid & 31;
    const int warp = tid >> 5;
    const int wm = warp % 2;
    const int wn = warp / 2;

    #pragma unroll
    for (int im = 0; im < 2; im++) {
        #pragma unroll
        for (int jn = 0; jn < 4; jn++) {
            const float* c = acc[im * 4 + jn];
            int n = n0 + wn * 32 + jn * 8 + (lane & 3) * 2;
            float b0 = __ldg(&bias[n]), b1 = __ldg(&bias[n + 1]);
            int r0 = m0 + wm * 32 + im * 16 + (lane >> 2);
            #pragma unroll
            for (int h = 0; h < 2; h++) {
                int m = r0 + h * 8;
                float v0 = c[2 * h + 0] + b0;
                float v1 = c[2 * h + 1] + b1;
                unsigned short h0, l0, h1, l1;
                split2(v0, h0, l0);
                split2(v1, h1, l1);
                uint32_t hp = (uint32_t)h0 | ((uint32_t)h1 << 16);
                uint32_t lp = (uint32_t)l0 | ((uint32_t)l1 << 16);
                size_t rowoff = (size_t)m * KSPL + n;
                if (z == 0) {   // pt: [hi, hi, lo]
                    *reinterpret_cast<uint32_t*>(P + rowoff) = hp;
                    *reinterpret_cast<uint32_t*>(P + rowoff + CDIM) = hp;
                    *reinterpret_cast<uint32_t*>(P + rowoff + 2 * CDIM) = lp;
                } else {        // pc: [hi, lo, hi]
                    *reinterpret_cast<uint32_t*>(P + rowoff) = hp;
                    *reinterpret_cast<uint32_t*>(P + rowoff + CDIM) = lp;
                    *reinterpret_cast<uint32_t*>(P + rowoff + 2 * CDIM) = hp;
                }
            }
        }
    }
}

// ============================================================
// K4: score GEMM (HMMA, 64x64 tiles, 256 thr, 2x4 warps):
// scores[b,i,j] = sigmoid(pt[b,i].pc[b,j]) + per-batch sums.
// ============================================================
__global__ void __launch_bounds__(256) score_hmma() {
    __shared__ __align__(16) __nv_bfloat16 sm[4 * SMAT];

    const int tid = threadIdx.x;
    const int b = blockIdx.z;
    const int i0 = blockIdx.y * 64;
    const int j0 = blockIdx.x * 64;

    const __nv_bfloat16* A = g_pt_s + (size_t)(b * LDIM + i0) * KSPL;
    const __nv_bfloat16* B = g_pc_s + (size_t)(b * LDIM + j0) * KSPL;

    float acc[4][4];   // MI=2, NJ=2
    #pragma unroll
    for (int i = 0; i < 4; i++)
        acc[i][0] = acc[i][1] = acc[i][2] = acc[i][3] = 0.0f;

    hmma_loop64<2, 4, 256>(A, B, sm, acc, tid);

    const int lane = tid & 31;
    const int warp = tid >> 5;
    const int wm = warp % 2;
    const int wn = warp / 2;     // 0..3

    float lsum = 0.0f;
    float* Sb = g_scores + ((size_t)b << 16);
    #pragma unroll
    for (int im = 0; im < 2; im++) {
        #pragma unroll
        for (int jn = 0; jn < 2; jn++) {
            const float* c = acc[im * 2 + jn];
            int j = j0 + wn * 16 + jn * 8 + (lane & 3) * 2;
            int r0 = i0 + wm * 32 + im * 16 + (lane >> 2);
            #pragma unroll
            for (int h = 0; h < 2; h++) {
                int i = r0 + h * 8;
                float s0 = sigmoid_fast(c[2 * h + 0]);
                float s1 = sigmoid_fast(c[2 * h + 1]);
                *reinterpret_cast<float2*>(Sb + (size_t)i * LDIM + j) =
                    make_float2(s0, s1);
                lsum += s0 + s1;
            }
        }
    }
    #pragma unroll
    for (int off = 16; off; off >>= 1)
        lsum += __shfl_xor_sync(0xFFFFFFFFu, lsum, off);
    __shared__ float red[8];
    if (lane == 0) red[warp] = lsum;
    __syncthreads();
    if (tid == 0) {
        float s = 0.0f;
        #pragma unroll
        for (int w = 0; w < 8; w++) s += red[w];
        atomicAdd(&g_Ssum[b], s);
    }
}

// ============================================================
// K5: cp_unnorm[b,c] = sum_{i,j} tanh(xd[b,i,c]*xt[b,j,c]) * scores[b,i,j]
// ============================================================
__global__ void __launch_bounds__(512) cp_kernel(const float* __restrict__ xd,
                                                 const float* __restrict__ xt) {
    const int b = blockIdx.y;
    const int i0 = blockIdx.x * 4;
    const int c = threadIdx.x;

    __shared__ float4 ws4[LDIM];
    {
        float* wsf = reinterpret_cast<float*>(ws4);
        const float* src = g_scores + (size_t)b * LDIM * LDIM + (size_t)i0 * LDIM;
        for (int t = threadIdx.x; t < 4 * LDIM; t += 512) {
            int i = t >> 8, j = t & (LDIM - 1);
            wsf[(j << 2) | i] = src[i * LDIM + j];
        }
    }

    const float* xdp = xd + ((size_t)(b * LDIM + i0)) * CDIM + c;
    const float xd0 = xdp[0 * CDIM];
    const float xd1 = xdp[1 * CDIM];
    const float xd2 = xdp[2 * CDIM];
    const float xd3 = xdp[3 * CDIM];
    __syncthreads();

    const float* xtp = xt + ((size_t)(b * LDIM)) * CDIM + c;
    float acc = 0.0f;
    #pragma unroll 4
    for (int j = 0; j < LDIM; j++) {
        float xtv = __ldg(&xtp[(size_t)j * CDIM]);
        float4 w = ws4[j];
        acc = fmaf(tanh_mufu(xd0 * xtv), w.x, acc);
        acc = fmaf(tanh_mufu(xd1 * xtv), w.y, acc);
        acc = fmaf(tanh_mufu(xd2 * xtv), w.z, acc);
        acc = fmaf(tanh_mufu(xd3 * xtv), w.w, acc);
    }
    atomicAdd(&g_cp[b * CDIM + c], acc);
}

// ============================================================
// K6: out[b,o] += (cp[b,:]/S_b) @ Wf[:,o]
// ============================================================
__global__ void out_gemm(const float* __restrict__ Wf, float* __restrict__ out) {
    const int b = blockIdx.x;
    const int c0 = blockIdx.y * 128;
    const int o = threadIdx.x;

    __shared__ float cps[128];
    float inv = __fdividef(1.0f, g_Ssum[b]);
    if (threadIdx.x < 128)
        cps[threadIdx.x] = g_cp[b * CDIM + c0 + threadIdx.x] * inv;
    __syncthreads();

    float acc = 0.0f;
    #pragma unroll 8
    for (int cc = 0; cc < 128; cc++)
        acc = fmaf(cps[cc], Wf[(c0 + cc) * ODIM + o], acc);
    atomicAdd(&out[b * ODIM + o], acc);
}

// ============================================================
extern "C" void kernel_launch(void* const* d_in, const int* in_sizes, int n_in,
                              void* d_out, int out_size) {
    const float* xd = (const float*)d_in[0];
    const float* xt = (const float*)d_in[1];
    const float* Wc = (const float*)d_in[2];
    const float* bc = (const float*)d_in[3];
    const float* Wp = (const float*)d_in[4];
    const float* bp = (const float*)d_in[5];
    const float* Wf = (const float*)d_in[6];
    const float* bf = (const float*)d_in[7];
    float* out = (float*)d_out;

    init_kernel<<<8, 512>>>(bf, out);
    split_x_kernel<<<dim3(MTOT * CDIM / 4 / 256, 1, 2), 256>>>(xt, xd);
    split_w_kernel<<<dim3(16, 16, 2), dim3(32, 32)>>>(Wp, Wc);
    proj_hmma<<<dim3(CDIM / 64, MTOT / 64, 2), 128>>>(bp, bc);
    score_hmma<<<dim3(LDIM / 64, LDIM / 64, BDIM), 256>>>();
    cp_kernel<<<dim3(LDIM / 4, BDIM), 512>>>(xd, xt);
    out_gemm<<<dim3(BDIM, 4), 512>>>(Wf, out);
}